// round 4
// baseline (speedup 1.0000x reference)
#include <cuda_runtime.h>
#include <cuda_bf16.h>
#include <cstdint>

// Sparsemax along last dim (n = 512) of a (64, 1024, 512) fp32 tensor.
// One warp per row; 16 elements per lane kept in registers.
// tau found by Michelot's iterative thresholding (exact fixed point of the
// sort-based sparsemax threshold), no sorting, no shared memory.

#define ROW_N   512
#define ELEMS   16          // per lane: 512 / 32
#define WARPS_PER_BLOCK 8
#define THREADS (WARPS_PER_BLOCK * 32)

__device__ __forceinline__ float warp_sum(float v) {
    #pragma unroll
    for (int m = 16; m > 0; m >>= 1)
        v += __shfl_xor_sync(0xFFFFFFFFu, v, m);
    return v;
}

__global__ __launch_bounds__(THREADS)
void sparsemax_kernel(const float* __restrict__ x,
                      float* __restrict__ out,
                      int rows) {
    const int warp_id = blockIdx.x * WARPS_PER_BLOCK + (threadIdx.x >> 5);
    if (warp_id >= rows) return;
    const int lane = threadIdx.x & 31;

    const float4* __restrict__ xin =
        reinterpret_cast<const float4*>(x + (size_t)warp_id * ROW_N);

    // Coalesced load: lane l grabs float4 indices l, l+32, l+64, l+96.
    float z[ELEMS];
    #pragma unroll
    for (int j = 0; j < 4; j++) {
        float4 v = xin[lane + 32 * j];
        z[4 * j + 0] = v.x;
        z[4 * j + 1] = v.y;
        z[4 * j + 2] = v.z;
        z[4 * j + 3] = v.w;
    }

    // Initial tau from the full set.
    float s = 0.0f;
    #pragma unroll
    for (int i = 0; i < ELEMS; i++) s += z[i];
    s = warp_sum(s);
    float tau = (s - 1.0f) * (1.0f / (float)ROW_N);
    int   cnt = ROW_N;

    // Michelot iteration: shrink support until stable.
    // Guaranteed finite (support strictly shrinks); cap defensively.
    #pragma unroll 1
    for (int it = 0; it < 64; it++) {
        float ps = 0.0f;
        int   pc = 0;
        #pragma unroll
        for (int i = 0; i < ELEMS; i++) {
            bool g = z[i] > tau;
            ps += g ? z[i] : 0.0f;
            pc += g ? 1 : 0;
        }
        ps = warp_sum(ps);
        pc = __reduce_add_sync(0xFFFFFFFFu, pc);
        if (pc == cnt) break;          // support stable -> tau is the fixed point
        cnt = pc;
        tau = (ps - 1.0f) / (float)pc;
    }

    // Write max(x - tau, 0), coalesced float4 stores.
    float4* __restrict__ o =
        reinterpret_cast<float4*>(out + (size_t)warp_id * ROW_N);
    #pragma unroll
    for (int j = 0; j < 4; j++) {
        float4 v;
        v.x = fmaxf(z[4 * j + 0] - tau, 0.0f);
        v.y = fmaxf(z[4 * j + 1] - tau, 0.0f);
        v.z = fmaxf(z[4 * j + 2] - tau, 0.0f);
        v.w = fmaxf(z[4 * j + 3] - tau, 0.0f);
        o[lane + 32 * j] = v;
    }
}

extern "C" void kernel_launch(void* const* d_in, const int* in_sizes, int n_in,
                              void* d_out, int out_size) {
    const float* x = (const float*)d_in[0];
    float* out = (float*)d_out;
    const int rows = in_sizes[0] / ROW_N;   // 64*1024 = 65536
    const int blocks = (rows + WARPS_PER_BLOCK - 1) / WARPS_PER_BLOCK;
    sparsemax_kernel<<<blocks, THREADS>>>(x, out, rows);
}

// round 5
// speedup vs baseline: 1.3326x; 1.3326x over previous
#include <cuda_runtime.h>
#include <cuda_bf16.h>
#include <cstdint>

// Sparsemax along last dim (n = 512) of a (64, 1024, 512) fp32 tensor.
// One warp per row; 16 elements per lane kept in registers.
//
// tau* is the unique fixed point of Michelot's thresholding iteration.
// Hard bound: tau* >= max(z) - 1 (output sums to 1, max element is in the
// support), so the support is a subset of {z > max-1}. We seed the iteration
// from that set: tau0 = (sum_{z>max-1} - 1)/k0 <= tau*, and the iteration
// converges monotonically to the exact sort-based threshold in ~3 steps
// instead of ~9 from the full-set seed.

#define ROW_N   512
#define ELEMS   16          // per lane: 512 / 32
#define WARPS_PER_BLOCK 8
#define THREADS (WARPS_PER_BLOCK * 32)

__device__ __forceinline__ float warp_sum(float v) {
    #pragma unroll
    for (int m = 16; m > 0; m >>= 1)
        v += __shfl_xor_sync(0xFFFFFFFFu, v, m);
    return v;
}

__device__ __forceinline__ float warp_max(float v) {
    #pragma unroll
    for (int m = 16; m > 0; m >>= 1)
        v = fmaxf(v, __shfl_xor_sync(0xFFFFFFFFu, v, m));
    return v;
}

__global__ __launch_bounds__(THREADS)
void sparsemax_kernel(const float* __restrict__ x,
                      float* __restrict__ out,
                      int rows) {
    const int warp_id = blockIdx.x * WARPS_PER_BLOCK + (threadIdx.x >> 5);
    if (warp_id >= rows) return;
    const int lane = threadIdx.x & 31;

    const float4* __restrict__ xin =
        reinterpret_cast<const float4*>(x + (size_t)warp_id * ROW_N);

    // Coalesced load: lane l grabs float4 indices l, l+32, l+64, l+96.
    float z[ELEMS];
    #pragma unroll
    for (int j = 0; j < 4; j++) {
        float4 v = xin[lane + 32 * j];
        z[4 * j + 0] = v.x;
        z[4 * j + 1] = v.y;
        z[4 * j + 2] = v.z;
        z[4 * j + 3] = v.w;
    }

    // Row max -> lower bound on tau*: thr = m - 1.
    float m = z[0];
    #pragma unroll
    for (int i = 1; i < ELEMS; i++) m = fmaxf(m, z[i]);
    m = warp_max(m);
    const float thr = m - 1.0f;

    // Seed from candidate set {z > m-1} (superset of the true support).
    float ps = 0.0f;
    int   pc = 0;
    #pragma unroll
    for (int i = 0; i < ELEMS; i++) {
        bool g = z[i] > thr;
        ps += g ? z[i] : 0.0f;
        pc += g ? 1 : 0;
    }
    ps = warp_sum(ps);
    pc = __reduce_add_sync(0xFFFFFFFFu, pc);
    float tau = __fdividef(ps - 1.0f, (float)pc);   // <= tau*, guaranteed
    int   cnt = pc;

    // Michelot iteration to the exact fixed point (typically 2-4 passes).
    #pragma unroll 1
    for (int it = 0; it < 48; it++) {
        float s = 0.0f;
        int   c = 0;
        #pragma unroll
        for (int i = 0; i < ELEMS; i++) {
            bool g = z[i] > tau;
            s += g ? z[i] : 0.0f;
            c += g ? 1 : 0;
        }
        s = warp_sum(s);
        c = __reduce_add_sync(0xFFFFFFFFu, c);
        if (c == cnt) break;            // support stable -> tau is the fixed point
        cnt = c;
        tau = __fdividef(s - 1.0f, (float)c);
    }

    // Write max(z - tau, 0), coalesced float4 stores.
    float4* __restrict__ o =
        reinterpret_cast<float4*>(out + (size_t)warp_id * ROW_N);
    #pragma unroll
    for (int j = 0; j < 4; j++) {
        float4 v;
        v.x = fmaxf(z[4 * j + 0] - tau, 0.0f);
        v.y = fmaxf(z[4 * j + 1] - tau, 0.0f);
        v.z = fmaxf(z[4 * j + 2] - tau, 0.0f);
        v.w = fmaxf(z[4 * j + 3] - tau, 0.0f);
        o[lane + 32 * j] = v;
    }
}

extern "C" void kernel_launch(void* const* d_in, const int* in_sizes, int n_in,
                              void* d_out, int out_size) {
    const float* x = (const float*)d_in[0];
    float* out = (float*)d_out;
    const int rows = in_sizes[0] / ROW_N;   // 64*1024 = 65536
    const int blocks = (rows + WARPS_PER_BLOCK - 1) / WARPS_PER_BLOCK;
    sparsemax_kernel<<<blocks, THREADS>>>(x, out, rows);
}

// round 9
// speedup vs baseline: 1.3816x; 1.0368x over previous
#include <cuda_runtime.h>
#include <cuda_bf16.h>
#include <cstdint>

// Sparsemax along last dim (n = 512) of a (64, 1024, 512) fp32 tensor.
// One warp per row, 16 elements/lane in registers.
//
// tau* >= max(z) - 1, so the support is a subset of C = {z > max-1}
// (|C| ~ 7 for N(0,1) rows). Each lane compacts its candidates into 2
// registers; Michelot's iteration then runs on the compacted set only
// (exact: the restricted iteration's unique fixed point equals the
// full-set threshold, since excluded elements can never enter the
// support). Warps where any lane holds >2 candidates (<5% of rows)
// take a full-scan fallback.

#define ROW_N   512
#define ELEMS   16
#define WARPS_PER_BLOCK 8
#define THREADS (WARPS_PER_BLOCK * 32)
#define FULLM   0xFFFFFFFFu

__device__ __forceinline__ float warp_sum(float v) {
    #pragma unroll
    for (int m = 16; m > 0; m >>= 1)
        v += __shfl_xor_sync(FULLM, v, m);
    return v;
}

__device__ __forceinline__ float warp_max(float v) {
    #pragma unroll
    for (int m = 16; m > 0; m >>= 1)
        v = fmaxf(v, __shfl_xor_sync(FULLM, v, m));
    return v;
}

__global__ __launch_bounds__(THREADS)
void sparsemax_kernel(const float* __restrict__ x,
                      float* __restrict__ out,
                      int rows) {
    const int warp_id = blockIdx.x * WARPS_PER_BLOCK + (threadIdx.x >> 5);
    if (warp_id >= rows) return;
    const int lane = threadIdx.x & 31;

    const float4* __restrict__ xin =
        reinterpret_cast<const float4*>(x + (size_t)warp_id * ROW_N);

    float z[ELEMS];
    #pragma unroll
    for (int j = 0; j < 4; j++) {
        float4 v = xin[lane + 32 * j];
        z[4 * j + 0] = v.x;
        z[4 * j + 1] = v.y;
        z[4 * j + 2] = v.z;
        z[4 * j + 3] = v.w;
    }

    // Row max -> candidate threshold thr = m - 1 (tau* >= thr).
    float m = z[0];
    #pragma unroll
    for (int i = 1; i < ELEMS; i++) m = fmaxf(m, z[i]);
    m = warp_max(m);
    const float thr = m - 1.0f;

    // Compact this lane's candidates {z > thr} into (v0, v1).
    const float NEG_INF = __int_as_float(0xff800000);
    float v0 = NEG_INF, v1 = NEG_INF;
    int nc = 0;
    #pragma unroll
    for (int i = 0; i < ELEMS; i++) {
        bool g = z[i] > thr;
        v1 = g ? v0 : v1;        // keep previous candidate
        v0 = g ? z[i] : v0;      // newest candidate
        nc += g ? 1 : 0;
    }

    float tau;
    const bool overflow = __ballot_sync(FULLM, nc > 2) != 0u;

    if (!overflow) {
        // ---- fast path: Michelot on <=2 candidates per lane ----
        float s = (v0 > thr ? v0 : 0.0f) + (v1 > thr ? v1 : 0.0f);
        int   c = nc;
        s = warp_sum(s);
        c = __reduce_add_sync(FULLM, c);
        tau = __fdividef(s - 1.0f, (float)c);
        int cnt = c;

        #pragma unroll 1
        for (int it = 0; it < 24; it++) {
            bool a = v0 > tau, b = v1 > tau;
            float s2 = (a ? v0 : 0.0f) + (b ? v1 : 0.0f);
            int   c2 = (a ? 1 : 0) + (b ? 1 : 0);
            s2 = warp_sum(s2);
            c2 = __reduce_add_sync(FULLM, c2);
            if (c2 == cnt) break;
            cnt = c2;
            tau = __fdividef(s2 - 1.0f, (float)c2);
        }
    } else {
        // ---- fallback: full 16-element scans (rare, warp-uniform) ----
        float ps = 0.0f;
        int   pc = 0;
        #pragma unroll
        for (int i = 0; i < ELEMS; i++) {
            bool g = z[i] > thr;
            ps += g ? z[i] : 0.0f;
            pc += g ? 1 : 0;
        }
        ps = warp_sum(ps);
        pc = __reduce_add_sync(FULLM, pc);
        tau = __fdividef(ps - 1.0f, (float)pc);
        int cnt = pc;

        #pragma unroll 1
        for (int it = 0; it < 48; it++) {
            float s = 0.0f;
            int   c = 0;
            #pragma unroll
            for (int i = 0; i < ELEMS; i++) {
                bool g = z[i] > tau;
                s += g ? z[i] : 0.0f;
                c += g ? 1 : 0;
            }
            s = warp_sum(s);
            c = __reduce_add_sync(FULLM, c);
            if (c == cnt) break;
            cnt = c;
            tau = __fdividef(s - 1.0f, (float)c);
        }
    }

    // Epilogue: max(z - tau, 0), coalesced float4 stores.
    float4* __restrict__ o =
        reinterpret_cast<float4*>(out + (size_t)warp_id * ROW_N);
    #pragma unroll
    for (int j = 0; j < 4; j++) {
        float4 v;
        v.x = fmaxf(z[4 * j + 0] - tau, 0.0f);
        v.y = fmaxf(z[4 * j + 1] - tau, 0.0f);
        v.z = fmaxf(z[4 * j + 2] - tau, 0.0f);
        v.w = fmaxf(z[4 * j + 3] - tau, 0.0f);
        o[lane + 32 * j] = v;
    }
}

extern "C" void kernel_launch(void* const* d_in, const int* in_sizes, int n_in,
                              void* d_out, int out_size) {
    const float* x = (const float*)d_in[0];
    float* out = (float*)d_out;
    const int rows = in_sizes[0] / ROW_N;   // 65536
    const int blocks = (rows + WARPS_PER_BLOCK - 1) / WARPS_PER_BLOCK;
    sparsemax_kernel<<<blocks, THREADS>>>(x, out, rows);
}